// round 1
// baseline (speedup 1.0000x reference)
#include <cuda_runtime.h>
#include <cuda_bf16.h>
#include <mma.h>

using namespace nvcuda;

// Problem constants
#define PB   8192      // batch
#define PDIM 4096      // model dim (= K for both GEMMs, = N)
#define PHID 256       // per-head hidden
#define PH   16        // heads
#define PSEQ 2048
// DECAY_CONSTANT = SEQ/512 = 4  -> exponent 0.25

// Scratch: hidden [B, H*HID] = [8192, 4096] fp32
__device__ float g_hidden[(size_t)PB * PDIM];
// Per-head coefficients: w[16], cache_coef[16], b[16]
__device__ float g_coef[48];

__global__ void coef_kernel(const float* __restrict__ w_mix,
                            const float* __restrict__ b_mix,
                            const float* __restrict__ decay_values,
                            const int* __restrict__ index_p) {
    int h = threadIdx.x;
    if (h < PH) {
        int idx = *index_p;
        float w = w_mix[h * PSEQ + idx];
        float b = b_mix[h * PSEQ + idx];
        float d = decay_values[h];
        d = fminf(fmaxf(d, 0.9f), 1.0f);
        d = powf(d, 0.25f);
        float cc = (h < PH / 2) ? (w * d) : d;
        g_coef[h]      = w;
        g_coef[16 + h] = cc;
        g_coef[32 + h] = b;
    }
}

// Tiled TF32 WMMA GEMM: C[M,N] = A[M,K] @ B[K,N] + epilogue
//   MODE 1: B = W_proj (per-head [DIM,HID] blocks, ldb=HID), epilogue:
//           C = w[h]*(acc + b_proj[h,k]) + cc[h]*caches[h,b,k] + b[h]
//   MODE 2: B = W_out (ldb=N), epilogue: C = acc + bias[n]
// Block tile 128x128x32, 256 threads, 8 warps each computing 32x64.
template <int MODE>
__global__ void __launch_bounds__(256)
gemm_tf32_kernel(const float* __restrict__ A,
                 const float* __restrict__ Bsrc,
                 const float* __restrict__ bias,
                 const float* __restrict__ caches,
                 float* __restrict__ C,
                 int M, int N, int K) {
    constexpr int BM = 128, BN = 128, BK = 32;
    constexpr int LDA_S = BK + 4;    // 36 (x4B = 144B, 16B-aligned rows)
    constexpr int LDB_S = BN + 4;    // 132 (x4B = 528B, 16B-aligned rows)

    __shared__ float As[BM][LDA_S];
    __shared__ float Bs[BK][LDB_S];
    __shared__ float stage[8][16 * 20];   // per-warp 16x16 epilogue staging (ld=20)

    const int m0 = blockIdx.y * BM;
    const int n0 = blockIdx.x * BN;
    const int tid  = threadIdx.x;
    const int warp = tid >> 5;
    const int lane = tid & 31;
    const int wm = warp & 3;   // 4 warps along M -> 32 rows each
    const int wn = warp >> 2;  // 2 warps along N -> 64 cols each

    // Resolve B base pointer + leading dim
    const float* Bbase;
    int ldb;
    int hhead = 0;
    if (MODE == 1) {
        hhead = n0 >> 8;                // head index (BN=128 tile within one 256-wide head)
        int kh = n0 & 255;              // column offset within head
        Bbase = Bsrc + (size_t)hhead * K * PHID + kh;
        ldb = PHID;
    } else {
        Bbase = Bsrc + n0;
        ldb = N;
    }

    wmma::fragment<wmma::accumulator, 16, 16, 8, float> acc[2][4];
#pragma unroll
    for (int i = 0; i < 2; i++)
#pragma unroll
        for (int j = 0; j < 4; j++) wmma::fill_fragment(acc[i][j], 0.0f);

    for (int k0 = 0; k0 < K; k0 += BK) {
        // Load A tile: 128x32 = 1024 float4, 4 per thread
#pragma unroll
        for (int i = 0; i < 4; i++) {
            int idx = tid + i * 256;
            int r = idx >> 3, c4 = idx & 7;
            float4 v = *(const float4*)(A + (size_t)(m0 + r) * K + k0 + c4 * 4);
            *(float4*)&As[r][c4 * 4] = v;
        }
        // Load B tile: 32x128 = 1024 float4, 4 per thread
#pragma unroll
        for (int i = 0; i < 4; i++) {
            int idx = tid + i * 256;
            int r = idx >> 5, c4 = idx & 31;
            float4 v = *(const float4*)(Bbase + (size_t)(k0 + r) * ldb + c4 * 4);
            *(float4*)&Bs[r][c4 * 4] = v;
        }
        __syncthreads();

#pragma unroll
        for (int ks = 0; ks < BK / 8; ks++) {
            wmma::fragment<wmma::matrix_a, 16, 16, 8, wmma::precision::tf32, wmma::row_major> af[2];
            wmma::fragment<wmma::matrix_b, 16, 16, 8, wmma::precision::tf32, wmma::row_major> bf[4];
#pragma unroll
            for (int i = 0; i < 2; i++) {
                wmma::load_matrix_sync(af[i], &As[wm * 32 + i * 16][ks * 8], LDA_S);
#pragma unroll
                for (int t = 0; t < af[i].num_elements; t++)
                    af[i].x[t] = wmma::__float_to_tf32(af[i].x[t]);
            }
#pragma unroll
            for (int j = 0; j < 4; j++) {
                wmma::load_matrix_sync(bf[j], &Bs[ks * 8][wn * 64 + j * 16], LDB_S);
#pragma unroll
                for (int t = 0; t < bf[j].num_elements; t++)
                    bf[j].x[t] = wmma::__float_to_tf32(bf[j].x[t]);
            }
#pragma unroll
            for (int i = 0; i < 2; i++)
#pragma unroll
                for (int j = 0; j < 4; j++)
                    wmma::mma_sync(acc[i][j], af[i], bf[j], acc[i][j]);
        }
        __syncthreads();
    }

    // Epilogue
    float wv = 0.f, cc = 0.f, bv = 0.f;
    if (MODE == 1) {
        wv = g_coef[hhead];
        cc = g_coef[16 + hhead];
        bv = g_coef[32 + hhead];
    }

#pragma unroll
    for (int i = 0; i < 2; i++) {
#pragma unroll
        for (int j = 0; j < 4; j++) {
            wmma::store_matrix_sync(&stage[warp][0], acc[i][j], 20, wmma::mem_row_major);
            __syncwarp();
            const int gr0 = m0 + wm * 32 + i * 16;
            const int gc0 = n0 + wn * 64 + j * 16;
#pragma unroll
            for (int e = lane; e < 256; e += 32) {
                int r = e >> 4, c = e & 15;
                float v = stage[warp][r * 20 + c];
                int gr = gr0 + r;
                int gc = gc0 + c;
                if (MODE == 1) {
                    int kk = gc & 255;
                    v = wv * (v + bias[hhead * PHID + kk])
                        + cc * caches[((size_t)hhead * M + gr) * PHID + kk]
                        + bv;
                } else {
                    v = v + bias[gc];
                }
                C[(size_t)gr * N + gc] = v;
            }
            __syncwarp();
        }
    }
}

extern "C" void kernel_launch(void* const* d_in, const int* in_sizes, int n_in,
                              void* d_out, int out_size) {
    const float* x       = (const float*)d_in[0];
    const int*   index_p = (const int*)  d_in[1];
    const float* W_proj  = (const float*)d_in[2];
    const float* b_proj  = (const float*)d_in[3];
    const float* W_out   = (const float*)d_in[4];
    const float* b_out   = (const float*)d_in[5];
    const float* w_mix   = (const float*)d_in[6];
    const float* b_mix   = (const float*)d_in[7];
    const float* decay   = (const float*)d_in[8];
    const float* caches  = (const float*)d_in[9];
    float* out = (float*)d_out;

    float* hidden = nullptr;
    cudaGetSymbolAddress((void**)&hidden, g_hidden);

    coef_kernel<<<1, 32>>>(w_mix, b_mix, decay, index_p);

    dim3 grid(PDIM / 128, PB / 128);   // (32, 64)
    gemm_tf32_kernel<1><<<grid, 256>>>(x, W_proj, b_proj, caches, hidden,
                                       PB, PDIM, PDIM);
    gemm_tf32_kernel<2><<<grid, 256>>>(hidden, W_out, b_out, nullptr, out,
                                       PB, PDIM, PDIM);
}

// round 4
// speedup vs baseline: 3.8183x; 3.8183x over previous
#include <cuda_runtime.h>
#include <cstdint>

#define PB   8192
#define PDIM 4096
#define PHID 256
#define PH   16
#define PSEQ 2048

// -------- device-global scratch (no allocs allowed) --------
__device__ float g_hidden[(size_t)PB * PDIM];      // 128 MB (tf32-rounded GEMM1 out)
__device__ float g_X[(size_t)PB * PDIM];           // 128 MB (tf32-rounded x)
__device__ float g_Wpt[(size_t)PH * PHID * PDIM];  // 64 MB  [n_global][k], tf32-rounded
__device__ float g_Wot[(size_t)PDIM * PDIM];       // 64 MB  [n][k], tf32-rounded
__device__ float g_coef[48];                       // w[16], cc[16], b[16]

// -------- helpers --------
__device__ __forceinline__ uint32_t smem_u32(const void* p) {
    uint32_t a;
    asm("{ .reg .u64 t; cvta.to.shared.u64 t, %1; cvt.u32.u64 %0, t; }" : "=r"(a) : "l"(p));
    return a;
}
__device__ __forceinline__ void cp16(uint32_t dst, const float* src) {
    asm volatile("cp.async.cg.shared.global [%0], [%1], 16;" :: "r"(dst), "l"(src));
}
__device__ __forceinline__ float rna_tf32(float v) {
    uint32_t u;
    asm("cvt.rna.tf32.f32 %0, %1;" : "=r"(u) : "f"(v));
    return __uint_as_float(u);
}
__device__ __forceinline__ void ldsm4(uint32_t* r, uint32_t addr) {
    asm volatile("ldmatrix.sync.aligned.m8n8.x4.shared.b16 {%0,%1,%2,%3}, [%4];"
                 : "=r"(r[0]), "=r"(r[1]), "=r"(r[2]), "=r"(r[3]) : "r"(addr));
}
__device__ __forceinline__ void mma_tf32(float* d, const uint32_t* a, const uint32_t* b) {
    asm volatile("mma.sync.aligned.m16n8k8.row.col.f32.tf32.tf32.f32 "
                 "{%0,%1,%2,%3}, {%4,%5,%6,%7}, {%8,%9}, {%0,%1,%2,%3};"
                 : "+f"(d[0]), "+f"(d[1]), "+f"(d[2]), "+f"(d[3])
                 : "r"(a[0]), "r"(a[1]), "r"(a[2]), "r"(a[3]), "r"(b[0]), "r"(b[1]));
}

// -------- small prep kernels --------
__global__ void coef_kernel(const float* __restrict__ w_mix,
                            const float* __restrict__ b_mix,
                            const float* __restrict__ decay_values,
                            const int* __restrict__ index_p) {
    int h = threadIdx.x;
    if (h < PH) {
        int idx = *index_p;
        float w = w_mix[h * PSEQ + idx];
        float b = b_mix[h * PSEQ + idx];
        float d = decay_values[h];
        d = fminf(fmaxf(d, 0.9f), 1.0f);
        d = powf(d, 0.25f);
        g_coef[h]      = w;
        g_coef[16 + h] = (h < PH / 2) ? (w * d) : d;
        g_coef[32 + h] = b;
    }
}

// tf32-rna elementwise convert (float4)
__global__ void cvt_kernel(const float* __restrict__ in, float* __restrict__ out, int n4) {
    int i = blockIdx.x * blockDim.x + threadIdx.x;
    if (i < n4) {
        float4 v = ((const float4*)in)[i];
        v.x = rna_tf32(v.x); v.y = rna_tf32(v.y);
        v.z = rna_tf32(v.z); v.w = rna_tf32(v.w);
        ((float4*)out)[i] = v;
    }
}

// out[b][c][r] = rna(in[b][r][c])
__global__ void transpose_kernel(const float* __restrict__ in, float* __restrict__ out,
                                 int rows, int cols) {
    __shared__ float t[32][33];
    const size_t bo = (size_t)blockIdx.z * rows * cols;
    const float* In = in + bo;
    float* Out = out + bo;
    int r0 = blockIdx.y * 32, c0 = blockIdx.x * 32;
#pragma unroll
    for (int i = threadIdx.y; i < 32; i += 8)
        t[i][threadIdx.x] = In[(size_t)(r0 + i) * cols + c0 + threadIdx.x];
    __syncthreads();
#pragma unroll
    for (int i = threadIdx.y; i < 32; i += 8)
        Out[(size_t)(c0 + i) * rows + r0 + threadIdx.x] = rna_tf32(t[threadIdx.x][i]);
}

// -------- TF32 mma.sync GEMM: C[8192,4096] = A[8192,4096] @ Bt[4096,4096]^T --------
// Bt is [N][K] k-contiguous. Tile 128x256x32, 8 warps (2Mx4N), 64x64 warp tile,
// 4-stage cp.async, SW128 xor swizzle, ldmatrix.x4.b16 operand loads.
// MODE 1: head epilogue (+ rna to hidden); MODE 2: + bias.
template <int MODE>
__global__ void __launch_bounds__(256, 1)
gemm_mma(const float* __restrict__ A, const float* __restrict__ Bt,
         const float* __restrict__ bias, const float* __restrict__ caches,
         float* __restrict__ C) {
    constexpr int S = 4;
    constexpr int NCH = PDIM / 32;        // 128
    constexpr uint32_t A_BYTES = 128 * 128;   // 16 KB
    constexpr uint32_t STG = A_BYTES + 256 * 128;  // 48 KB

    extern __shared__ char smem[];
    const uint32_t sb = smem_u32(smem);
    const int tid = threadIdx.x;
    const int wid = tid >> 5, lane = tid & 31;
    const int wm = wid & 1;      // 2 warps along M
    const int wn = wid >> 1;     // 4 warps along N

    const int m0 = blockIdx.y * 128;
    const int n0 = blockIdx.x * 256;
    const float* Ab = A + (size_t)m0 * PDIM;
    const float* Bb = Bt + (size_t)n0 * PDIM;

    // per-thread cp.async coordinates (A: 4 chunks of 16B, B: 8 chunks)
    int ar[4], ac[4]; uint32_t asw[4];
    int br[8], bc[8]; uint32_t bsw[8];
#pragma unroll
    for (int j = 0; j < 4; j++) {
        int id = tid + j * 256;
        ar[j] = id >> 3; ac[j] = id & 7;
        asw[j] = (uint32_t)ar[j] * 128 + ((((uint32_t)ac[j]) * 16) ^ ((((uint32_t)ar[j]) & 7) << 4));
    }
#pragma unroll
    for (int j = 0; j < 8; j++) {
        int id = tid + j * 256;
        br[j] = id >> 3; bc[j] = id & 7;
        bsw[j] = (uint32_t)br[j] * 128 + ((((uint32_t)bc[j]) * 16) ^ ((((uint32_t)br[j]) & 7) << 4));
    }

    float acc[4][8][4];
#pragma unroll
    for (int mt = 0; mt < 4; mt++)
#pragma unroll
        for (int nt = 0; nt < 8; nt++)
#pragma unroll
            for (int e = 0; e < 4; e++) acc[mt][nt][e] = 0.0f;

    // ldmatrix per-thread base coords
    const int a_row = wm * 64 + (lane & 15);         // + mt*16
    const int a_grp = (lane >> 4);                   // + 2*ks
    const int b_row = wn * 64 + (lane & 7) + ((lane >> 4) << 3);   // + ntp*16
    const int b_grp = (lane >> 3) & 1;               // + 2*ks

    auto issue = [&](int c) {
        const float* ag = Ab + c * 32;
        const float* bg = Bb + c * 32;
        uint32_t st = sb + (uint32_t)(c & (S - 1)) * STG;
#pragma unroll
        for (int j = 0; j < 4; j++)
            cp16(st + asw[j], ag + (size_t)ar[j] * PDIM + ac[j] * 4);
#pragma unroll
        for (int j = 0; j < 8; j++)
            cp16(st + A_BYTES + bsw[j], bg + (size_t)br[j] * PDIM + bc[j] * 4);
    };

    // prologue: 3 stages
#pragma unroll
    for (int c = 0; c < S - 1; c++) {
        issue(c);
        asm volatile("cp.async.commit_group;" ::: "memory");
    }

    for (int i = 0; i < NCH; i++) {
        asm volatile("cp.async.wait_group %0;" :: "n"(S - 2) : "memory");
        __syncthreads();

        uint32_t sa = sb + (uint32_t)(i & (S - 1)) * STG;
        uint32_t sB = sa + A_BYTES;

#pragma unroll
        for (int ks = 0; ks < 4; ks++) {
            uint32_t af[4][4], bf[4][4];
#pragma unroll
            for (int mt = 0; mt < 4; mt++) {
                int rr = a_row + mt * 16;
                int gg = 2 * ks + a_grp;
                ldsm4(af[mt], sa + (uint32_t)rr * 128 +
                              ((((uint32_t)gg) << 4) ^ ((((uint32_t)rr) & 7) << 4)));
            }
#pragma unroll
            for (int ntp = 0; ntp < 4; ntp++) {
                int rr = b_row + ntp * 16;
                int gg = 2 * ks + b_grp;
                ldsm4(bf[ntp], sB + (uint32_t)rr * 128 +
                               ((((uint32_t)gg) << 4) ^ ((((uint32_t)rr) & 7) << 4)));
            }
#pragma unroll
            for (int mt = 0; mt < 4; mt++)
#pragma unroll
                for (int nt = 0; nt < 8; nt++)
                    mma_tf32(acc[mt][nt], af[mt], &bf[nt >> 1][(nt & 1) * 2]);
        }

        int c = i + S - 1;
        if (c < NCH) issue(c);
        asm volatile("cp.async.commit_group;" ::: "memory");
    }

    // -------- epilogue --------
    const int r = lane >> 2, qc = lane & 3;
    float wv = 0.f, ccf = 0.f, bvv = 0.f;
    if (MODE == 1) {
        wv  = g_coef[blockIdx.x];
        ccf = g_coef[16 + blockIdx.x];
        bvv = g_coef[32 + blockIdx.x];
    }
#pragma unroll
    for (int mt = 0; mt < 4; mt++) {
        const int grow0 = m0 + wm * 64 + mt * 16 + r;
#pragma unroll
        for (int nt = 0; nt < 8; nt++) {
            const int cloc = wn * 64 + nt * 8 + 2 * qc;   // col within 256-wide tile
            const int gcol = n0 + cloc;
            if (MODE == 1) {
                const float2 bp = *(const float2*)&bias[blockIdx.x * PHID + cloc];
#pragma unroll
                for (int h2 = 0; h2 < 2; h2++) {
                    const int grow = grow0 + h2 * 8;
                    const float2 cv = *(const float2*)
                        &caches[((size_t)blockIdx.x * PB + grow) * PHID + cloc];
                    float2 o;
                    o.x = rna_tf32(wv * (acc[mt][nt][h2 * 2 + 0] + bp.x) + ccf * cv.x + bvv);
                    o.y = rna_tf32(wv * (acc[mt][nt][h2 * 2 + 1] + bp.y) + ccf * cv.y + bvv);
                    *(float2*)&C[(size_t)grow * PDIM + gcol] = o;
                }
            } else {
                const float2 bp = *(const float2*)&bias[gcol];
#pragma unroll
                for (int h2 = 0; h2 < 2; h2++) {
                    const int grow = grow0 + h2 * 8;
                    float2 o;
                    o.x = acc[mt][nt][h2 * 2 + 0] + bp.x;
                    o.y = acc[mt][nt][h2 * 2 + 1] + bp.y;
                    *(float2*)&C[(size_t)grow * PDIM + gcol] = o;
                }
            }
        }
    }
}

// -------- launch --------
extern "C" void kernel_launch(void* const* d_in, const int* in_sizes, int n_in,
                              void* d_out, int out_size) {
    const float* x       = (const float*)d_in[0];
    const int*   index_p = (const int*)  d_in[1];
    const float* W_proj  = (const float*)d_in[2];
    const float* b_proj  = (const float*)d_in[3];
    const float* W_out   = (const float*)d_in[4];
    const float* b_out   = (const float*)d_in[5];
    const float* w_mix   = (const float*)d_in[6];
    const float* b_mix   = (const float*)d_in[7];
    const float* decay   = (const float*)d_in[8];
    const float* caches  = (const float*)d_in[9];
    float* out = (float*)d_out;

    float *hidden, *xr, *wpt, *wot;
    cudaGetSymbolAddress((void**)&hidden, g_hidden);
    cudaGetSymbolAddress((void**)&xr,     g_X);
    cudaGetSymbolAddress((void**)&wpt,    g_Wpt);
    cudaGetSymbolAddress((void**)&wot,    g_Wot);

    const int SMEM_TOTAL = 4 * (128 * 128 + 256 * 128);   // 196608
    cudaFuncSetAttribute(gemm_mma<1>, cudaFuncAttributeMaxDynamicSharedMemorySize, SMEM_TOTAL);
    cudaFuncSetAttribute(gemm_mma<2>, cudaFuncAttributeMaxDynamicSharedMemorySize, SMEM_TOTAL);

    coef_kernel<<<1, 32>>>(w_mix, b_mix, decay, index_p);

    // x -> rna(tf32)
    {
        int n4 = (int)(((size_t)PB * PDIM) / 4);
        cvt_kernel<<<(n4 + 255) / 256, 256>>>(x, xr, n4);
    }
    // W_proj [16][4096][256] -> g_Wpt [16][256][4096] (rna)
    transpose_kernel<<<dim3(PHID / 32, PDIM / 32, PH), dim3(32, 8)>>>(W_proj, wpt, PDIM, PHID);
    // W_out [4096][4096] -> g_Wot [N][K] (rna)
    transpose_kernel<<<dim3(PDIM / 32, PDIM / 32, 1), dim3(32, 8)>>>(W_out, wot, PDIM, PDIM);

    dim3 grid(PDIM / 256, PB / 128);   // (16, 64)
    gemm_mma<1><<<grid, 256, SMEM_TOTAL>>>(xr, wpt, b_proj, caches, hidden);
    gemm_mma<2><<<grid, 256, SMEM_TOTAL>>>(hidden, wot, b_out, nullptr, out);
}